// round 8
// baseline (speedup 1.0000x reference)
#include <cuda_runtime.h>

#define NB 32
#define NT 8192
#define NC 1024
#define NH 16
#define SCALE 0.03125f   // 1024^-0.5

#define TILE_R 256
#define KC 32
#define NCH (NC / KC)            // 32 chunks

// ---- scratch ----
__device__ float g_scores[(size_t)NB * NT * NH];
__device__ float g_Z[NB * NH];
__device__ float g_pooled[NB * NC];
__device__ float g_qT[NC * NH];          // qT[c][h]

__device__ __forceinline__ void ffma2(unsigned long long& d,
                                      unsigned long long a,
                                      unsigned long long b) {
    asm("fma.rn.f32x2 %0, %1, %2, %0;" : "+l"(d) : "l"(a), "l"(b));
}
__device__ __forceinline__ unsigned long long add2(unsigned long long a,
                                                   unsigned long long b) {
    unsigned long long r;
    asm("add.rn.f32x2 %0, %1, %2;" : "=l"(r) : "l"(a), "l"(b));
    return r;
}
__device__ __forceinline__ unsigned long long pack2(float v) {
    unsigned long long r;
    asm("mov.b64 %0, {%1, %1};" : "=l"(r) : "f"(v));
    return r;
}
__device__ __forceinline__ float lo2(unsigned long long a) { return __uint_as_float((unsigned)a); }
__device__ __forceinline__ float hi2(unsigned long long a) { return __uint_as_float((unsigned)(a >> 32)); }

// ============================================================
// K0: zero accumulators + build qT[c][h]
// ============================================================
__global__ void k_zero(const float* __restrict__ q) {
    int i = blockIdx.x * blockDim.x + threadIdx.x;
    if (i < NB * NC) g_pooled[i] = 0.0f;
    if (i < NB * NH) g_Z[i] = 0.0f;
    if (i < NC * NH) {
        int c = i >> 4, h = i & 15;
        g_qT[i] = q[h * NC + c];
    }
}

// ============================================================
// K1: scores GEMM, x direct-from-GMEM (no staging, no inner barriers).
// CTA: 512 threads, 256 rows x 16 heads.
// headg = tid>>8 (head half), crow = (tid&255)>>2 (64 rows, x4 = 256),
// chg = tid&3 (8-channel slice of each 32-ch chunk).
// Accums packed over HEAD pairs: acc[4 rows][4 head-pairs] f32x2.
// ============================================================
__global__ void __launch_bounds__(512, 1)
k_scores(const float* __restrict__ x) {
    extern __shared__ float qts[];       // qT staged: 1024*16 floats = 64 KB
    __shared__ float zsh[NH];

    const int b = blockIdx.y, tile = blockIdx.x, tid = threadIdx.x;
    const int headg = tid >> 8;
    const int t8 = tid & 255;
    const int crow = t8 >> 2, chg = t8 & 3;

    for (int i = tid; i < NC * NH / 4; i += 512)
        ((float4*)qts)[i] = ((const float4*)g_qT)[i];
    if (tid < NH) zsh[tid] = 0.0f;
    __syncthreads();

    const float* xb = x + ((size_t)(b * NT + tile * TILE_R)) * NC;

    unsigned long long acc[4][4];
    #pragma unroll
    for (int g = 0; g < 4; g++)
        #pragma unroll
        for (int k = 0; k < 4; k++) acc[g][k] = 0ull;

    for (int c = 0; c < NCH; c++) {
        // x: 4 rows x 8 channels, straight from GMEM (L1/L2 for 2nd head-half)
        float4 xv[4][2];
        #pragma unroll
        for (int g = 0; g < 4; g++) {
            const float* p = xb + (size_t)(crow + 64 * g) * NC + c * KC + chg * 8;
            xv[g][0] = *(const float4*)(p);
            xv[g][1] = *(const float4*)(p + 4);
        }
        const float* qc = qts + (size_t)(c * KC + chg * 8) * NH + headg * 8;
        #pragma unroll
        for (int j = 0; j < 8; j++) {
            ulonglong2 qv0 = *(const ulonglong2*)(qc + j * NH);      // head-pairs 0,1
            ulonglong2 qv1 = *(const ulonglong2*)(qc + j * NH + 4);  // head-pairs 2,3
            #pragma unroll
            for (int g = 0; g < 4; g++) {
                const float xsv = ((const float*)&xv[g][0])[j];  // static index
                unsigned long long x2 = pack2(xsv);
                ffma2(acc[g][0], x2, qv0.x);
                ffma2(acc[g][1], x2, qv0.y);
                ffma2(acc[g][2], x2, qv1.x);
                ffma2(acc[g][3], x2, qv1.y);
            }
        }
    }

    // reduce over the 4 channel-lanes (xor 1, 2)
    #pragma unroll
    for (int st = 1; st <= 2; st <<= 1)
        #pragma unroll
        for (int g = 0; g < 4; g++)
            #pragma unroll
            for (int k = 0; k < 4; k++)
                acc[g][k] = add2(acc[g][k],
                                 __shfl_xor_sync(0xffffffffu, acc[g][k], st));

    float zacc[8];
    #pragma unroll
    for (int k = 0; k < 8; k++) zacc[k] = 0.0f;

    if (chg == 0) {
        #pragma unroll
        for (int g = 0; g < 4; g++) {
            int rr = tile * TILE_R + crow + 64 * g;
            float s[8];
            #pragma unroll
            for (int k = 0; k < 4; k++) {
                s[2 * k]     = lo2(acc[g][k]) * SCALE;
                s[2 * k + 1] = hi2(acc[g][k]) * SCALE;
            }
            float* dst = g_scores + ((size_t)b * NT + rr) * NH + headg * 8;
            *(float4*)(dst + 0) = make_float4(s[0], s[1], s[2], s[3]);
            *(float4*)(dst + 4) = make_float4(s[4], s[5], s[6], s[7]);
            #pragma unroll
            for (int k = 0; k < 8; k++) zacc[k] += expf(s[k]);
        }
    }
    // warp-reduce Z across the chg==0 lanes (lanes 0,4,...,28; xor 4,8,16 closed)
    #pragma unroll
    for (int st = 4; st <= 16; st <<= 1)
        #pragma unroll
        for (int k = 0; k < 8; k++)
            zacc[k] += __shfl_xor_sync(0xffffffffu, zacc[k], st);
    if ((tid & 31) == 0) {
        #pragma unroll
        for (int k = 0; k < 8; k++)
            atomicAdd(&zsh[headg * 8 + k], zacc[k]);
    }
    __syncthreads();
    if (tid < NH) atomicAdd(&g_Z[b * NH + tid], zsh[tid]);
}

// ============================================================
// K2: pooled[b,c] += sum_t w[b,t]*x[b,t,c],  w = (1/16) sum_h exp(s)/Z_h
// ============================================================
__global__ void __launch_bounds__(256)
k_pool(const float* __restrict__ x) {
    __shared__ float ws[128];
    __shared__ float rz[16];
    const int b = blockIdx.y, tile = blockIdx.x, tid = threadIdx.x;

    if (tid < 16) rz[tid] = 1.0f / g_Z[b * NH + tid];
    __syncthreads();

    if (tid < 128) {
        const int r = tile * 128 + tid;
        const float4* sp = (const float4*)(g_scores + ((size_t)b * NT + r) * NH);
        float4 s0 = sp[0], s1 = sp[1], s2 = sp[2], s3 = sp[3];
        float w = expf(s0.x) * rz[0]  + expf(s0.y) * rz[1]
                + expf(s0.z) * rz[2]  + expf(s0.w) * rz[3]
                + expf(s1.x) * rz[4]  + expf(s1.y) * rz[5]
                + expf(s1.z) * rz[6]  + expf(s1.w) * rz[7]
                + expf(s2.x) * rz[8]  + expf(s2.y) * rz[9]
                + expf(s2.z) * rz[10] + expf(s2.w) * rz[11]
                + expf(s3.x) * rz[12] + expf(s3.y) * rz[13]
                + expf(s3.z) * rz[14] + expf(s3.w) * rz[15];
        ws[tid] = w * (1.0f / 16.0f);
    }
    __syncthreads();

    const int c = tid * 4;
    float4 a0 = make_float4(0.f, 0.f, 0.f, 0.f);
    float4 a1 = make_float4(0.f, 0.f, 0.f, 0.f);
    const float* xb = x + ((size_t)b * NT + tile * 128) * NC + c;
    #pragma unroll 4
    for (int r = 0; r < 128; r += 2) {
        float4 x0 = *(const float4*)(xb + (size_t)r * NC);
        float4 x1 = *(const float4*)(xb + (size_t)(r + 1) * NC);
        float w0 = ws[r], w1 = ws[r + 1];
        a0.x += w0 * x0.x; a0.y += w0 * x0.y; a0.z += w0 * x0.z; a0.w += w0 * x0.w;
        a1.x += w1 * x1.x; a1.y += w1 * x1.y; a1.z += w1 * x1.z; a1.w += w1 * x1.w;
    }
    float* pp = g_pooled + b * NC + c;
    atomicAdd(pp + 0, a0.x + a1.x);
    atomicAdd(pp + 1, a0.y + a1.y);
    atomicAdd(pp + 2, a0.z + a1.z);
    atomicAdd(pp + 3, a0.w + a1.w);
}

// ============================================================
// K3: out[b,j] = <pooled[b,:], W[j,:]> + bias[j]
// ============================================================
__global__ void __launch_bounds__(256)
k_proj(const float* __restrict__ w, const float* __restrict__ bias,
       float* __restrict__ out) {
    const int warp = threadIdx.x >> 5, lane = threadIdx.x & 31;
    const int j = blockIdx.x * 8 + warp;

    float4 wr[8];
    const float4* wp = (const float4*)(w + (size_t)j * NC);
    #pragma unroll
    for (int i = 0; i < 8; i++) wr[i] = wp[lane + 32 * i];
    const float bj = bias[j];

    const int b0 = blockIdx.y * 8;
    for (int b = b0; b < b0 + 8; b++) {
        const float4* pp = (const float4*)(g_pooled + b * NC);
        float acc = 0.0f;
        #pragma unroll
        for (int i = 0; i < 8; i++) {
            float4 pv = pp[lane + 32 * i];
            acc += pv.x * wr[i].x + pv.y * wr[i].y
                 + pv.z * wr[i].z + pv.w * wr[i].w;
        }
        #pragma unroll
        for (int m = 16; m >= 1; m >>= 1)
            acc += __shfl_xor_sync(0xffffffffu, acc, m);
        if (lane == 0) out[b * NC + j] = acc + bj;
    }
}

// ============================================================
extern "C" void kernel_launch(void* const* d_in, const int* in_sizes, int n_in,
                              void* d_out, int out_size) {
    const float* x  = (const float*)d_in[0];
    const float* q  = (const float*)d_in[1];
    const float* pw = (const float*)d_in[2];
    const float* pb = (const float*)d_in[3];
    float* out      = (float*)d_out;

    const int smem = NC * NH * (int)sizeof(float);   // 64 KB
    cudaFuncSetAttribute(k_scores, cudaFuncAttributeMaxDynamicSharedMemorySize, smem);

    k_zero<<<128, 256>>>(q);
    k_scores<<<dim3(NT / TILE_R, NB), 512, smem>>>(x);
    k_pool<<<dim3(64, NB), 256>>>(x);
    k_proj<<<dim3(128, 4), 256>>>(pw, pb, out);
}

// round 9
// speedup vs baseline: 1.5984x; 1.5984x over previous
#include <cuda_runtime.h>

#define NB 32
#define NT 8192
#define NC 1024
#define NH 16
#define SCALE 0.03125f   // 1024^-0.5

#define TILE_R 256
#define KC 32
#define XSTR 36                  // 32 + 4 pad: conflict-free phases
#define NCH (NC / KC)            // 32 chunks

// ---- scratch ----
__device__ float g_scores[(size_t)NB * NT * NH];
__device__ float g_Z[NB * NH];
__device__ float g_pooled[NB * NC];

__device__ __forceinline__ void ffma2(unsigned long long& d,
                                      unsigned long long a,
                                      unsigned long long b) {
    asm("fma.rn.f32x2 %0, %1, %2, %0;" : "+l"(d) : "l"(a), "l"(b));
}
__device__ __forceinline__ float lo2(unsigned long long a) { return __uint_as_float((unsigned)a); }
__device__ __forceinline__ float hi2(unsigned long long a) { return __uint_as_float((unsigned)(a >> 32)); }

// ============================================================
__global__ void k_zero() {
    int i = blockIdx.x * blockDim.x + threadIdx.x;
    if (i < NB * NC) g_pooled[i] = 0.0f;
    if (i < NB * NH) g_Z[i] = 0.0f;
}

// ============================================================
// K1: scores GEMM. CTA: 256 rows x 16 heads, 128 threads
// (64 rowg x 2 headg), thread tile 4 rows x 8 heads (f32x2 over
// channel parity). KC=32 chunks -> 32 sync-pairs per tile (half of R3)
// and 4-line coalesced warp-LDGs (8 lanes per 128B row).
// ============================================================
__global__ void __launch_bounds__(128, 2)
k_scores(const float* __restrict__ x, const float* __restrict__ q) {
    extern __shared__ float sm[];
    float* qs = sm;                      // 16*1024 floats (64 KB)
    float* xs = sm + NH * NC;            // 256*36 floats  (36 KB)
    __shared__ float zsh[NH];

    const int b = blockIdx.y, tile = blockIdx.x, tid = threadIdx.x;
    const int rowg = tid & 63, headg = tid >> 6;      // 64 x 2
    const int crow = tid >> 3, ccol = (tid & 7) * 4;  // copy: 8 lanes/row

    for (int i = tid; i < NH * NC / 4; i += 128)
        ((float4*)qs)[i] = ((const float4*)q)[i];
    if (tid < NH) zsh[tid] = 0.0f;

    const float* xb = x + ((size_t)(b * NT + tile * TILE_R)) * NC;

    float4 r[16];
#define LOADC(c)                                                            \
    _Pragma("unroll")                                                       \
    for (int g = 0; g < 16; g++)                                            \
        r[g] = *(const float4*)(xb + (size_t)(g * 16 + crow) * NC           \
                                + (c) * KC + ccol);
    LOADC(0);

    unsigned long long acc[4][8];
    #pragma unroll
    for (int m = 0; m < 4; m++)
        #pragma unroll
        for (int h = 0; h < 8; h++) acc[m][h] = 0ull;

    for (int c = 0; c < NCH; c++) {
        #pragma unroll
        for (int g = 0; g < 16; g++)
            *(float4*)(xs + (g * 16 + crow) * XSTR + ccol) = r[g];
        __syncthreads();

        if (c + 1 < NCH) { LOADC(c + 1); }   // LDGs overlap compute

        const float* qc = qs + (size_t)headg * 8 * NC + c * KC;
        #pragma unroll
        for (int j = 0; j < 8; j++) {        // 4 channels per step
            ulonglong2 xv[4];
            #pragma unroll
            for (int m = 0; m < 4; m++)
                xv[m] = *(const ulonglong2*)(xs + (rowg + 64 * m) * XSTR + 4 * j);
            #pragma unroll
            for (int h = 0; h < 8; h++) {
                ulonglong2 qv = *(const ulonglong2*)(qc + h * NC + 4 * j); // broadcast
                #pragma unroll
                for (int m = 0; m < 4; m++) {
                    ffma2(acc[m][h], xv[m].x, qv.x);
                    ffma2(acc[m][h], xv[m].y, qv.y);
                }
            }
        }
        __syncthreads();
    }
#undef LOADC

    float zacc[8];
    #pragma unroll
    for (int h = 0; h < 8; h++) zacc[h] = 0.0f;

    #pragma unroll
    for (int m = 0; m < 4; m++) {
        int rr = tile * TILE_R + rowg + 64 * m;
        float s[8];
        #pragma unroll
        for (int h = 0; h < 8; h++) {
            s[h] = (lo2(acc[m][h]) + hi2(acc[m][h])) * SCALE;
            zacc[h] += expf(s[h]);
        }
        float* dst = g_scores + ((size_t)b * NT + rr) * NH + headg * 8;
        *(float4*)(dst + 0) = make_float4(s[0], s[1], s[2], s[3]);
        *(float4*)(dst + 4) = make_float4(s[4], s[5], s[6], s[7]);
    }
    #pragma unroll
    for (int h = 0; h < 8; h++) {
        float v = zacc[h];
        #pragma unroll
        for (int m2 = 16; m2 >= 1; m2 >>= 1)
            v += __shfl_xor_sync(0xffffffffu, v, m2);
        if ((tid & 31) == 0) atomicAdd(&zsh[headg * 8 + h], v);
    }
    __syncthreads();
    if (tid < NH) atomicAdd(&g_Z[b * NH + tid], zsh[tid]);
}

// ============================================================
// K2: pooled[b,c] += sum_t w[b,t]*x[b,t,c],  w = (1/16) sum_h exp(s)/Z_h
// 4-row inner step for MLP=8 front-batched LDG.128.
// ============================================================
__global__ void __launch_bounds__(256)
k_pool(const float* __restrict__ x) {
    __shared__ float ws[128];
    __shared__ float rz[16];
    const int b = blockIdx.y, tile = blockIdx.x, tid = threadIdx.x;

    if (tid < 16) rz[tid] = 1.0f / g_Z[b * NH + tid];
    __syncthreads();

    if (tid < 128) {
        const int r = tile * 128 + tid;
        const float4* sp = (const float4*)(g_scores + ((size_t)b * NT + r) * NH);
        float4 s0 = sp[0], s1 = sp[1], s2 = sp[2], s3 = sp[3];
        float w = expf(s0.x) * rz[0]  + expf(s0.y) * rz[1]
                + expf(s0.z) * rz[2]  + expf(s0.w) * rz[3]
                + expf(s1.x) * rz[4]  + expf(s1.y) * rz[5]
                + expf(s1.z) * rz[6]  + expf(s1.w) * rz[7]
                + expf(s2.x) * rz[8]  + expf(s2.y) * rz[9]
                + expf(s2.z) * rz[10] + expf(s2.w) * rz[11]
                + expf(s3.x) * rz[12] + expf(s3.y) * rz[13]
                + expf(s3.z) * rz[14] + expf(s3.w) * rz[15];
        ws[tid] = w * (1.0f / 16.0f);
    }
    __syncthreads();

    const int c = tid * 4;
    float4 a0 = make_float4(0.f, 0.f, 0.f, 0.f);
    float4 a1 = make_float4(0.f, 0.f, 0.f, 0.f);
    float4 a2 = make_float4(0.f, 0.f, 0.f, 0.f);
    float4 a3 = make_float4(0.f, 0.f, 0.f, 0.f);
    const float* xb = x + ((size_t)b * NT + tile * 128) * NC + c;
    #pragma unroll 2
    for (int r = 0; r < 128; r += 4) {
        float4 x0 = *(const float4*)(xb + (size_t)(r + 0) * NC);
        float4 x1 = *(const float4*)(xb + (size_t)(r + 1) * NC);
        float4 x2 = *(const float4*)(xb + (size_t)(r + 2) * NC);
        float4 x3 = *(const float4*)(xb + (size_t)(r + 3) * NC);
        float w0 = ws[r], w1 = ws[r + 1], w2 = ws[r + 2], w3 = ws[r + 3];
        a0.x += w0 * x0.x; a0.y += w0 * x0.y; a0.z += w0 * x0.z; a0.w += w0 * x0.w;
        a1.x += w1 * x1.x; a1.y += w1 * x1.y; a1.z += w1 * x1.z; a1.w += w1 * x1.w;
        a2.x += w2 * x2.x; a2.y += w2 * x2.y; a2.z += w2 * x2.z; a2.w += w2 * x2.w;
        a3.x += w3 * x3.x; a3.y += w3 * x3.y; a3.z += w3 * x3.z; a3.w += w3 * x3.w;
    }
    float* pp = g_pooled + b * NC + c;
    atomicAdd(pp + 0, (a0.x + a1.x) + (a2.x + a3.x));
    atomicAdd(pp + 1, (a0.y + a1.y) + (a2.y + a3.y));
    atomicAdd(pp + 2, (a0.z + a1.z) + (a2.z + a3.z));
    atomicAdd(pp + 3, (a0.w + a1.w) + (a2.w + a3.w));
}

// ============================================================
// K3: out[b,j] = <pooled[b,:], W[j,:]> + bias[j]
// ============================================================
__global__ void __launch_bounds__(256)
k_proj(const float* __restrict__ w, const float* __restrict__ bias,
       float* __restrict__ out) {
    const int warp = threadIdx.x >> 5, lane = threadIdx.x & 31;
    const int j = blockIdx.x * 8 + warp;

    float4 wr[8];
    const float4* wp = (const float4*)(w + (size_t)j * NC);
    #pragma unroll
    for (int i = 0; i < 8; i++) wr[i] = wp[lane + 32 * i];
    const float bj = bias[j];

    const int b0 = blockIdx.y * 8;
    for (int b = b0; b < b0 + 8; b++) {
        const float4* pp = (const float4*)(g_pooled + b * NC);
        float acc = 0.0f;
        #pragma unroll
        for (int i = 0; i < 8; i++) {
            float4 pv = pp[lane + 32 * i];
            acc += pv.x * wr[i].x + pv.y * wr[i].y
                 + pv.z * wr[i].z + pv.w * wr[i].w;
        }
        #pragma unroll
        for (int m = 16; m >= 1; m >>= 1)
            acc += __shfl_xor_sync(0xffffffffu, acc, m);
        if (lane == 0) out[b * NC + j] = acc + bj;
    }
}

// ============================================================
extern "C" void kernel_launch(void* const* d_in, const int* in_sizes, int n_in,
                              void* d_out, int out_size) {
    const float* x  = (const float*)d_in[0];
    const float* q  = (const float*)d_in[1];
    const float* pw = (const float*)d_in[2];
    const float* pb = (const float*)d_in[3];
    float* out      = (float*)d_out;

    const int smem = (NH * NC + TILE_R * XSTR) * (int)sizeof(float);  // 100 KB
    cudaFuncSetAttribute(k_scores, cudaFuncAttributeMaxDynamicSharedMemorySize, smem);

    k_zero<<<128, 256>>>();
    k_scores<<<dim3(NT / TILE_R, NB), 128, smem>>>(x, q);
    k_pool<<<dim3(64, NB), 256>>>(x);
    k_proj<<<dim3(128, 4), 256>>>(pw, pb, out);
}

// round 10
// speedup vs baseline: 1.6000x; 1.0010x over previous
#include <cuda_runtime.h>

#define NB 32
#define NT 8192
#define NC 1024
#define NH 16
#define SCALE 0.03125f   // 1024^-0.5

#define TILE_R 256
#define KC 32
#define XSTR 36                  // 32 + 4 pad: conflict-free phases
#define NCH (NC / KC)            // 32 chunks

// ---- scratch ----
__device__ float g_scores[(size_t)NB * NT * NH];
__device__ float g_Z[NB * NH];
__device__ float g_pooled[NB * NC];

__device__ __forceinline__ void ffma2(unsigned long long& d,
                                      unsigned long long a,
                                      unsigned long long b) {
    asm("fma.rn.f32x2 %0, %1, %2, %0;" : "+l"(d) : "l"(a), "l"(b));
}
__device__ __forceinline__ float lo2(unsigned long long a) { return __uint_as_float((unsigned)a); }
__device__ __forceinline__ float hi2(unsigned long long a) { return __uint_as_float((unsigned)(a >> 32)); }

// ============================================================
__global__ void k_zero() {
    int i = blockIdx.x * blockDim.x + threadIdx.x;
    if (i < NB * NC) g_pooled[i] = 0.0f;
    if (i < NB * NH) g_Z[i] = 0.0f;
}

// ============================================================
// K1: scores GEMM. CTA: 256 rows x 16 heads, 128 threads
// (64 rowg x 2 headg), thread tile 4 rows x 8 heads (f32x2 over
// channel parity). KC=32 chunks -> 32 sync-pairs per tile (half of R3)
// and 4-line coalesced warp-LDGs (8 lanes per 128B row).
// ============================================================
__global__ void __launch_bounds__(128, 2)
k_scores(const float* __restrict__ x, const float* __restrict__ q) {
    extern __shared__ float sm[];
    float* qs = sm;                      // 16*1024 floats (64 KB)
    float* xs = sm + NH * NC;            // 256*36 floats  (36 KB)
    __shared__ float zsh[NH];

    const int b = blockIdx.y, tile = blockIdx.x, tid = threadIdx.x;
    const int rowg = tid & 63, headg = tid >> 6;      // 64 x 2
    const int crow = tid >> 3, ccol = (tid & 7) * 4;  // copy: 8 lanes/row

    for (int i = tid; i < NH * NC / 4; i += 128)
        ((float4*)qs)[i] = ((const float4*)q)[i];
    if (tid < NH) zsh[tid] = 0.0f;

    const float* xb = x + ((size_t)(b * NT + tile * TILE_R)) * NC;

    float4 r[16];
#define LOADC(c)                                                            \
    _Pragma("unroll")                                                       \
    for (int g = 0; g < 16; g++)                                            \
        r[g] = *(const float4*)(xb + (size_t)(g * 16 + crow) * NC           \
                                + (c) * KC + ccol);
    LOADC(0);

    unsigned long long acc[4][8];
    #pragma unroll
    for (int m = 0; m < 4; m++)
        #pragma unroll
        for (int h = 0; h < 8; h++) acc[m][h] = 0ull;

    for (int c = 0; c < NCH; c++) {
        #pragma unroll
        for (int g = 0; g < 16; g++)
            *(float4*)(xs + (g * 16 + crow) * XSTR + ccol) = r[g];
        __syncthreads();

        if (c + 1 < NCH) { LOADC(c + 1); }   // LDGs overlap compute

        const float* qc = qs + (size_t)headg * 8 * NC + c * KC;
        #pragma unroll
        for (int j = 0; j < 8; j++) {        // 4 channels per step
            ulonglong2 xv[4];
            #pragma unroll
            for (int m = 0; m < 4; m++)
                xv[m] = *(const ulonglong2*)(xs + (rowg + 64 * m) * XSTR + 4 * j);
            #pragma unroll
            for (int h = 0; h < 8; h++) {
                ulonglong2 qv = *(const ulonglong2*)(qc + h * NC + 4 * j); // broadcast
                #pragma unroll
                for (int m = 0; m < 4; m++) {
                    ffma2(acc[m][h], xv[m].x, qv.x);
                    ffma2(acc[m][h], xv[m].y, qv.y);
                }
            }
        }
        __syncthreads();
    }
#undef LOADC

    float zacc[8];
    #pragma unroll
    for (int h = 0; h < 8; h++) zacc[h] = 0.0f;

    #pragma unroll
    for (int m = 0; m < 4; m++) {
        int rr = tile * TILE_R + rowg + 64 * m;
        float s[8];
        #pragma unroll
        for (int h = 0; h < 8; h++) {
            s[h] = (lo2(acc[m][h]) + hi2(acc[m][h])) * SCALE;
            zacc[h] += expf(s[h]);
        }
        float* dst = g_scores + ((size_t)b * NT + rr) * NH + headg * 8;
        *(float4*)(dst + 0) = make_float4(s[0], s[1], s[2], s[3]);
        *(float4*)(dst + 4) = make_float4(s[4], s[5], s[6], s[7]);
    }
    #pragma unroll
    for (int h = 0; h < 8; h++) {
        float v = zacc[h];
        #pragma unroll
        for (int m2 = 16; m2 >= 1; m2 >>= 1)
            v += __shfl_xor_sync(0xffffffffu, v, m2);
        if ((tid & 31) == 0) atomicAdd(&zsh[headg * 8 + h], v);
    }
    __syncthreads();
    if (tid < NH) atomicAdd(&g_Z[b * NH + tid], zsh[tid]);
}

// ============================================================
// K2: pooled[b,c] += sum_t w[b,t]*x[b,t,c],  w = (1/16) sum_h exp(s)/Z_h
// 4-row inner step for MLP=8 front-batched LDG.128.
// ============================================================
__global__ void __launch_bounds__(256)
k_pool(const float* __restrict__ x) {
    __shared__ float ws[128];
    __shared__ float rz[16];
    const int b = blockIdx.y, tile = blockIdx.x, tid = threadIdx.x;

    if (tid < 16) rz[tid] = 1.0f / g_Z[b * NH + tid];
    __syncthreads();

    if (tid < 128) {
        const int r = tile * 128 + tid;
        const float4* sp = (const float4*)(g_scores + ((size_t)b * NT + r) * NH);
        float4 s0 = sp[0], s1 = sp[1], s2 = sp[2], s3 = sp[3];
        float w = expf(s0.x) * rz[0]  + expf(s0.y) * rz[1]
                + expf(s0.z) * rz[2]  + expf(s0.w) * rz[3]
                + expf(s1.x) * rz[4]  + expf(s1.y) * rz[5]
                + expf(s1.z) * rz[6]  + expf(s1.w) * rz[7]
                + expf(s2.x) * rz[8]  + expf(s2.y) * rz[9]
                + expf(s2.z) * rz[10] + expf(s2.w) * rz[11]
                + expf(s3.x) * rz[12] + expf(s3.y) * rz[13]
                + expf(s3.z) * rz[14] + expf(s3.w) * rz[15];
        ws[tid] = w * (1.0f / 16.0f);
    }
    __syncthreads();

    const int c = tid * 4;
    float4 a0 = make_float4(0.f, 0.f, 0.f, 0.f);
    float4 a1 = make_float4(0.f, 0.f, 0.f, 0.f);
    float4 a2 = make_float4(0.f, 0.f, 0.f, 0.f);
    float4 a3 = make_float4(0.f, 0.f, 0.f, 0.f);
    const float* xb = x + ((size_t)b * NT + tile * 128) * NC + c;
    #pragma unroll 2
    for (int r = 0; r < 128; r += 4) {
        float4 x0 = *(const float4*)(xb + (size_t)(r + 0) * NC);
        float4 x1 = *(const float4*)(xb + (size_t)(r + 1) * NC);
        float4 x2 = *(const float4*)(xb + (size_t)(r + 2) * NC);
        float4 x3 = *(const float4*)(xb + (size_t)(r + 3) * NC);
        float w0 = ws[r], w1 = ws[r + 1], w2 = ws[r + 2], w3 = ws[r + 3];
        a0.x += w0 * x0.x; a0.y += w0 * x0.y; a0.z += w0 * x0.z; a0.w += w0 * x0.w;
        a1.x += w1 * x1.x; a1.y += w1 * x1.y; a1.z += w1 * x1.z; a1.w += w1 * x1.w;
        a2.x += w2 * x2.x; a2.y += w2 * x2.y; a2.z += w2 * x2.z; a2.w += w2 * x2.w;
        a3.x += w3 * x3.x; a3.y += w3 * x3.y; a3.z += w3 * x3.z; a3.w += w3 * x3.w;
    }
    float* pp = g_pooled + b * NC + c;
    atomicAdd(pp + 0, (a0.x + a1.x) + (a2.x + a3.x));
    atomicAdd(pp + 1, (a0.y + a1.y) + (a2.y + a3.y));
    atomicAdd(pp + 2, (a0.z + a1.z) + (a2.z + a3.z));
    atomicAdd(pp + 3, (a0.w + a1.w) + (a2.w + a3.w));
}

// ============================================================
// K3: out[b,j] = <pooled[b,:], W[j,:]> + bias[j]
// ============================================================
__global__ void __launch_bounds__(256)
k_proj(const float* __restrict__ w, const float* __restrict__ bias,
       float* __restrict__ out) {
    const int warp = threadIdx.x >> 5, lane = threadIdx.x & 31;
    const int j = blockIdx.x * 8 + warp;

    float4 wr[8];
    const float4* wp = (const float4*)(w + (size_t)j * NC);
    #pragma unroll
    for (int i = 0; i < 8; i++) wr[i] = wp[lane + 32 * i];
    const float bj = bias[j];

    const int b0 = blockIdx.y * 8;
    for (int b = b0; b < b0 + 8; b++) {
        const float4* pp = (const float4*)(g_pooled + b * NC);
        float acc = 0.0f;
        #pragma unroll
        for (int i = 0; i < 8; i++) {
            float4 pv = pp[lane + 32 * i];
            acc += pv.x * wr[i].x + pv.y * wr[i].y
                 + pv.z * wr[i].z + pv.w * wr[i].w;
        }
        #pragma unroll
        for (int m = 16; m >= 1; m >>= 1)
            acc += __shfl_xor_sync(0xffffffffu, acc, m);
        if (lane == 0) out[b * NC + j] = acc + bj;
    }
}

// ============================================================
extern "C" void kernel_launch(void* const* d_in, const int* in_sizes, int n_in,
                              void* d_out, int out_size) {
    const float* x  = (const float*)d_in[0];
    const float* q  = (const float*)d_in[1];
    const float* pw = (const float*)d_in[2];
    const float* pb = (const float*)d_in[3];
    float* out      = (float*)d_out;

    const int smem = (NH * NC + TILE_R * XSTR) * (int)sizeof(float);  // 100 KB
    cudaFuncSetAttribute(k_scores, cudaFuncAttributeMaxDynamicSharedMemorySize, smem);

    k_zero<<<128, 256>>>();
    k_scores<<<dim3(NT / TILE_R, NB), 128, smem>>>(x, q);
    k_pool<<<dim3(64, NB), 256>>>(x);
    k_proj<<<dim3(128, 4), 256>>>(pw, pb, out);
}